// round 15
// baseline (speedup 1.0000x reference)
#include <cuda_runtime.h>
#include <cuda_bf16.h>
#include <math.h>
#include <limits.h>

// Problem constants (fixed by the reference)
#define N_NODES    12288
#define N_FEATURES 256
#define KEY_DIM    128
#define N_GRAPHS   192
#define QKV_COLS   512        // [Q(128) | K(128) | V(256)]

#define SPLIT 4               // row-split CTAs per graph for the score phase
#define NGMAX 128
#define KPAD  132             // score-kernel K row stride (fp32), 16B-aligned

typedef unsigned long long ull;
typedef unsigned int uint;

// Packed fp32x2 ops (score kernel)
__device__ __forceinline__ void ffma2(ull& d, ull a, ull b) {
    asm("fma.rn.f32x2 %0, %1, %2, %0;" : "+l"(d) : "l"(a), "l"(b));
}
__device__ __forceinline__ float2 unpack2(ull v) {
    float2 r; asm("mov.b64 {%0, %1}, %2;" : "=f"(r.x), "=f"(r.y) : "l"(v)); return r;
}
__device__ __forceinline__ ull addx2(ull a, ull b) {
    ull r; asm("add.rn.f32x2 %0, %1, %2;" : "=l"(r) : "l"(a), "l"(b)); return r;
}

// bf16 mma (HMMA.16816): D += A(16x16,row) * B(16x8,col), fp32 accum
__device__ __forceinline__ void mma16816(float* c, const uint* a, uint b0, uint b1) {
    asm("mma.sync.aligned.m16n8k16.row.col.f32.bf16.bf16.f32 "
        "{%0,%1,%2,%3}, {%4,%5,%6,%7}, {%8,%9}, {%0,%1,%2,%3};"
        : "+f"(c[0]), "+f"(c[1]), "+f"(c[2]), "+f"(c[3])
        : "r"(a[0]), "r"(a[1]), "r"(a[2]), "r"(a[3]), "r"(b0), "r"(b1));
}

__device__ __forceinline__ unsigned short bfbits(float x) {
    __nv_bfloat16 h = __float2bfloat16_rn(x);
    return *(unsigned short*)&h;
}
__device__ __forceinline__ float bf2f(unsigned short u) {
    __nv_bfloat16 h = *(__nv_bfloat16*)&u;
    return __bfloat162float(h);
}

// Static device scratch (no allocs)
__device__ float  g_QKV[N_NODES * QKV_COLS];                 // 25.2 MB
__device__ float  g_wpart[SPLIT * N_GRAPHS * NGMAX];         // partial colsums
__device__ int    g_start[N_GRAPHS];
__device__ int    g_end[N_GRAPHS];
__device__ unsigned short g_Xhi[N_NODES * N_FEATURES];       // 6.3 MB
__device__ unsigned short g_Xlo[N_NODES * N_FEATURES];       // 6.3 MB
__device__ unsigned short g_WhiT[QKV_COLS * N_FEATURES];     // 256 KB, [col][k]
__device__ unsigned short g_WloT[QKV_COLS * N_FEATURES];     // 256 KB

// ---------------------------------------------------------------------------
// Kernel 0: init per-graph ranges
// ---------------------------------------------------------------------------
__global__ void init_ranges_kernel() {
    int g = blockIdx.x * blockDim.x + threadIdx.x;
    if (g < N_GRAPHS) {
        g_start[g] = INT_MAX;
        g_end[g]   = 0;
    }
}

// ---------------------------------------------------------------------------
// Kernel 1: per-graph [start, end) from sorted batch (robust to int32/int64)
// ---------------------------------------------------------------------------
__global__ void compute_ranges_kernel(const void* __restrict__ batch) {
    int i = blockIdx.x * blockDim.x + threadIdx.x;
    if (i >= N_NODES) return;
    const long long* b64 = (const long long*)batch;
    long long probe = b64[N_NODES / 4];
    bool is32 = (probe < 0) || (probe >= (long long)N_GRAPHS);
    int g = is32 ? ((const int*)batch)[i] : (int)b64[i];
    if (g < 0 || g >= N_GRAPHS) return;   // defensive
    atomicMin(&g_start[g], i);
    atomicMax(&g_end[g], i + 1);
}

// ---------------------------------------------------------------------------
// Kernel 2a: split X into bf16 hi/lo (row-major, same layout as X)
// ---------------------------------------------------------------------------
__global__ __launch_bounds__(256)
void split_x_kernel(const float* __restrict__ X) {
    int t = blockIdx.x * 256 + threadIdx.x;      // one float4 per thread
    if (t >= N_NODES * N_FEATURES / 4) return;
    float4 v = ((const float4*)X)[t];
    ushort4 h, l;
    h.x = bfbits(v.x); l.x = bfbits(v.x - bf2f(h.x));
    h.y = bfbits(v.y); l.y = bfbits(v.y - bf2f(h.y));
    h.z = bfbits(v.z); l.z = bfbits(v.z - bf2f(h.z));
    h.w = bfbits(v.w); l.w = bfbits(v.w - bf2f(h.w));
    *(ushort4*)&g_Xhi[t * 4] = h;
    *(ushort4*)&g_Xlo[t * 4] = l;
}

// ---------------------------------------------------------------------------
// Kernel 2b: split + transpose W into [col 512][k 256] bf16 hi/lo.
// Column layout: [Wq(0..127) | Wk(128..255) | Wv(256..511)]
// ---------------------------------------------------------------------------
__global__ __launch_bounds__(256)
void split_w_kernel(const float* __restrict__ Wq,
                    const float* __restrict__ Wk,
                    const float* __restrict__ Wv) {
    int t = blockIdx.x * 256 + threadIdx.x;      // 512 cols x 32 k-chunks
    if (t >= QKV_COLS * (N_FEATURES / 8)) return;
    int col = t >> 5;
    int k0  = (t & 31) * 8;
    const float* W; int ldw, cl;
    if (col < 128)      { W = Wq; ldw = KEY_DIM;    cl = col;       }
    else if (col < 256) { W = Wk; ldw = KEY_DIM;    cl = col - 128; }
    else                { W = Wv; ldw = N_FEATURES; cl = col - 256; }
    ushort4 h0, h1, l0, l1;
    unsigned short hs[8], ls[8];
#pragma unroll
    for (int i = 0; i < 8; i++) {
        float x = W[(k0 + i) * ldw + cl];
        hs[i] = bfbits(x);
        ls[i] = bfbits(x - bf2f(hs[i]));
    }
    h0 = make_ushort4(hs[0], hs[1], hs[2], hs[3]);
    h1 = make_ushort4(hs[4], hs[5], hs[6], hs[7]);
    l0 = make_ushort4(ls[0], ls[1], ls[2], ls[3]);
    l1 = make_ushort4(ls[4], ls[5], ls[6], ls[7]);
    *(ushort4*)&g_WhiT[col * N_FEATURES + k0]     = h0;
    *(ushort4*)&g_WhiT[col * N_FEATURES + k0 + 4] = h1;
    *(ushort4*)&g_WloT[col * N_FEATURES + k0]     = l0;
    *(ushort4*)&g_WloT[col * N_FEATURES + k0 + 4] = l1;
}

// ---------------------------------------------------------------------------
// Kernel 3: tensor-core QKV GEMM (bf16-split, 3 passes, fp32 accum).
//   QKV[N,512] = X[N,256] @ Wcat[256,512]
// CTA: BM=128, BN=128 (grid (4 slabs, 96)); 8 warps in 4(M)x2(N);
// warp tile 32x64 = 2x8 m16n8k16 atoms. BK=32 (two k16 steps per tile).
// Smem rows padded to 40 bf16 -> conflict-free fragment LDS.
// ---------------------------------------------------------------------------
#define BKP 40

__global__ __launch_bounds__(256)
void qkv_gemm_tc_kernel() {
    __shared__ unsigned short Ahi[128 * BKP], Alo[128 * BKP];
    __shared__ unsigned short Bhi[128 * BKP], Blo[128 * BKP];

    const int bx = blockIdx.x;            // slab: global cols bx*128..+127
    const int by = blockIdx.y;            // row block
    const int tid  = threadIdx.x;
    const int wid  = tid >> 5;
    const int lane = tid & 31;
    const int warp_m = wid >> 1;          // 0..3
    const int warp_n = wid & 1;           // 0..1
    const int groupID = lane >> 2;        // 0..7
    const int tig     = lane & 3;         // 0..3
    const int row0  = by * 128;
    const int ncol0 = bx * 128;

    float acc[2][8][4];
#pragma unroll
    for (int am = 0; am < 2; am++)
#pragma unroll
        for (int an = 0; an < 8; an++)
#pragma unroll
            for (int q = 0; q < 4; q++) acc[am][an][q] = 0.0f;

    for (int tile = 0; tile < N_FEATURES / 32; tile++) {
        const int k0 = tile * 32;
        __syncthreads();
        // A tile: 128 rows x 32 k (hi+lo), contiguous uint4 copies
#pragma unroll
        for (int t = tid; t < 512; t += 256) {
            int r = t >> 2, c = (t & 3) * 8;
            *(uint4*)&Ahi[r * BKP + c] =
                *(const uint4*)&g_Xhi[(row0 + r) * N_FEATURES + k0 + c];
            *(uint4*)&Alo[r * BKP + c] =
                *(const uint4*)&g_Xlo[(row0 + r) * N_FEATURES + k0 + c];
        }
        // B tile: 128 n-rows x 32 k (hi+lo) from transposed W
#pragma unroll
        for (int t = tid; t < 512; t += 256) {
            int nn = t >> 2, c = (t & 3) * 8;
            *(uint4*)&Bhi[nn * BKP + c] =
                *(const uint4*)&g_WhiT[(ncol0 + nn) * N_FEATURES + k0 + c];
            *(uint4*)&Blo[nn * BKP + c] =
                *(const uint4*)&g_WloT[(ncol0 + nn) * N_FEATURES + k0 + c];
        }
        __syncthreads();

#pragma unroll
        for (int ks = 0; ks < 32; ks += 16) {
            uint ahi[2][4], alo[2][4];
#pragma unroll
            for (int am = 0; am < 2; am++) {
                int row = warp_m * 32 + am * 16 + groupID;
                int base = row * BKP + ks + tig * 2;
                ahi[am][0] = *(const uint*)&Ahi[base];
                ahi[am][1] = *(const uint*)&Ahi[base + 8 * BKP];
                ahi[am][2] = *(const uint*)&Ahi[base + 8];
                ahi[am][3] = *(const uint*)&Ahi[base + 8 * BKP + 8];
                alo[am][0] = *(const uint*)&Alo[base];
                alo[am][1] = *(const uint*)&Alo[base + 8 * BKP];
                alo[am][2] = *(const uint*)&Alo[base + 8];
                alo[am][3] = *(const uint*)&Alo[base + 8 * BKP + 8];
            }
#pragma unroll
            for (int an = 0; an < 8; an++) {
                int nn = warp_n * 64 + an * 8 + groupID;
                int nb = nn * BKP + ks + tig * 2;
                uint bh0 = *(const uint*)&Bhi[nb];
                uint bh1 = *(const uint*)&Bhi[nb + 8];
                uint bl0 = *(const uint*)&Blo[nb];
                uint bl1 = *(const uint*)&Blo[nb + 8];
#pragma unroll
                for (int am = 0; am < 2; am++) {
                    mma16816(acc[am][an], ahi[am], bh0, bh1);   // hi*hi
                    mma16816(acc[am][an], ahi[am], bl0, bl1);   // hi*lo
                    mma16816(acc[am][an], alo[am], bh0, bh1);   // lo*hi
                }
            }
        }
    }

    // Epilogue: c0,c1 -> (row, col..col+1); c2,c3 -> (row+8, ...)
#pragma unroll
    for (int am = 0; am < 2; am++) {
#pragma unroll
        for (int an = 0; an < 8; an++) {
            int row = row0 + warp_m * 32 + am * 16 + groupID;
            int col = ncol0 + warp_n * 64 + an * 8 + tig * 2;
            *(float2*)&g_QKV[(size_t)row * QKV_COLS + col] =
                make_float2(acc[am][an][0], acc[am][an][1]);
            *(float2*)&g_QKV[(size_t)(row + 8) * QKV_COLS + col] =
                make_float2(acc[am][an][2], acc[am][an][3]);
        }
    }
}

// ---------------------------------------------------------------------------
// Kernel 4: score phase (unchanged from round 13 — protected win).
// ---------------------------------------------------------------------------
#define SC_SMEM_FLOATS (NGMAX * KPAD + 8 * NGMAX + 8 * KEY_DIM)
#define SC_SMEM_BYTES  (SC_SMEM_FLOATS * 4)

__global__ __launch_bounds__(256, 3)
void attn_score_kernel() {
    extern __shared__ float sm[];
    float* sK   = sm;                         // NGMAX * KPAD
    float* wcol = sK + NGMAX * KPAD;          // 8 * NGMAX
    float* sQ   = wcol + 8 * NGMAX;           // 8 * 128

    const int r    = blockIdx.x;
    const int g    = blockIdx.y;
    const int tid  = threadIdx.x;
    const int w    = tid >> 5;
    const int lane = tid & 31;
    const int gw   = r * 8 + w;

    int s = g_start[g];
    int n = g_end[g] - s;
    if (n <= 0) return;
    if (n > NGMAX) n = NGMAX;

    for (int t = tid; t < n * (KEY_DIM / 4); t += 256) {
        int j = t >> 5;
        int k = (t & 31) << 2;
        float4 v = *(const float4*)&g_QKV[(s + j) * QKV_COLS + KEY_DIM + k];
        *(float4*)&sK[j * KPAD + k] = v;
    }
    __syncthreads();

    float wsum[4] = {0.0f, 0.0f, 0.0f, 0.0f};

    for (int i = gw; i < n; i += SPLIT * 8) {
        {
            float4 v = *(const float4*)&g_QKV[(s + i) * QKV_COLS + lane * 4];
            *(float4*)&sQ[w * KEY_DIM + lane * 4] = v;
        }
        __syncwarp();

        const ulonglong2* q4 = (const ulonglong2*)&sQ[w * KEY_DIM];
        float sc[4];
        float m = -INFINITY;
        int nj = 0;
        for (int j = lane; j < n; j += 32) {
            const ulonglong2* k4 = (const ulonglong2*)&sK[j * KPAD];
            ull a0 = 0, a1 = 0, a2v = 0, a3 = 0;
#pragma unroll 4
            for (int kk = 0; kk < KEY_DIM / 4; kk += 2) {
                ulonglong2 qa = q4[kk], qb = q4[kk + 1];
                ulonglong2 ka = k4[kk], kb = k4[kk + 1];
                ffma2(a0,  qa.x, ka.x);
                ffma2(a1,  qa.y, ka.y);
                ffma2(a2v, qb.x, kb.x);
                ffma2(a3,  qb.y, kb.y);
            }
            float2 t2 = unpack2(addx2(addx2(a0, a1), addx2(a2v, a3)));
            float d = (t2.x + t2.y) * 0.0625f;
            sc[nj++] = d;
            m = fmaxf(m, d);
        }
#pragma unroll
        for (int o = 16; o > 0; o >>= 1) m = fmaxf(m, __shfl_xor_sync(0xffffffffu, m, o));
        float ssum = 0.0f;
#pragma unroll
        for (int q = 0; q < 4; q++)
            if (q < nj) { sc[q] = __expf(sc[q] - m); ssum += sc[q]; }
#pragma unroll
        for (int o = 16; o > 0; o >>= 1) ssum += __shfl_xor_sync(0xffffffffu, ssum, o);
        const float inv = 1.0f / ssum;
#pragma unroll
        for (int q = 0; q < 4; q++)
            if (q < nj) wsum[q] += sc[q] * inv;
        __syncwarp();
    }

#pragma unroll
    for (int q = 0; q < 4; q++) {
        int j = lane + 32 * q;
        if (j < NGMAX) wcol[w * NGMAX + j] = wsum[q];
    }
    __syncthreads();

    for (int j = tid; j < n; j += 256) {
        float t = 0.0f;
#pragma unroll
        for (int ww = 0; ww < 8; ww++) t += wcol[ww * NGMAX + j];
        g_wpart[(r * N_GRAPHS + g) * NGMAX + j] = t;
    }
}

// ---------------------------------------------------------------------------
// Kernel 5: final reduce + weighted V sum (unchanged from round 13).
// ---------------------------------------------------------------------------
__global__ __launch_bounds__(128)
void attn_out_kernel(float* __restrict__ out) {
    __shared__ float colsum[NGMAX];

    const int fz  = blockIdx.x;
    const int g   = blockIdx.y;
    const int tid = threadIdx.x;
    const int f   = fz * 128 + tid;

    int s = g_start[g];
    int n = g_end[g] - s;
    if (n <= 0) {
        out[g * N_FEATURES + f] = 0.0f;
        return;
    }
    if (n > NGMAX) n = NGMAX;

    {
        int j = tid;
        float t = 0.0f;
        if (j < n) {
#pragma unroll
            for (int r = 0; r < SPLIT; r++)
                t += g_wpart[(r * N_GRAPHS + g) * NGMAX + j];
        }
        colsum[j] = t;
    }
    __syncthreads();

    const float* Vb = &g_QKV[(size_t)s * QKV_COLS + 2 * KEY_DIM + f];
    float a0 = 0.0f, a1 = 0.0f, a2 = 0.0f, a3 = 0.0f;
    int j = 0;
    for (; j + 3 < n; j += 4) {
        a0 += colsum[j + 0] * Vb[(size_t)(j + 0) * QKV_COLS];
        a1 += colsum[j + 1] * Vb[(size_t)(j + 1) * QKV_COLS];
        a2 += colsum[j + 2] * Vb[(size_t)(j + 2) * QKV_COLS];
        a3 += colsum[j + 3] * Vb[(size_t)(j + 3) * QKV_COLS];
    }
    for (; j < n; j++) a0 += colsum[j] * Vb[(size_t)j * QKV_COLS];
    out[g * N_FEATURES + f] = (a0 + a1) + (a2 + a3);
}

// ---------------------------------------------------------------------------
// Launch
// ---------------------------------------------------------------------------
extern "C" void kernel_launch(void* const* d_in, const int* in_sizes, int n_in,
                              void* d_out, int out_size) {
    const float* X  = (const float*)d_in[0];
    const void*  batch = d_in[1];
    const float* Wq = (const float*)d_in[2];
    const float* Wk = (const float*)d_in[3];
    const float* Wv = (const float*)d_in[4];
    float* out = (float*)d_out;

    cudaFuncSetAttribute(attn_score_kernel,
                         cudaFuncAttributeMaxDynamicSharedMemorySize,
                         SC_SMEM_BYTES);

    init_ranges_kernel<<<1, N_GRAPHS>>>();
    compute_ranges_kernel<<<(N_NODES + 255) / 256, 256>>>(batch);
    split_x_kernel<<<(N_NODES * N_FEATURES / 4 + 255) / 256, 256>>>(X);
    split_w_kernel<<<(QKV_COLS * (N_FEATURES / 8) + 255) / 256, 256>>>(Wq, Wk, Wv);
    qkv_gemm_tc_kernel<<<dim3(4, N_NODES / 128), 256>>>();
    attn_score_kernel<<<dim3(SPLIT, N_GRAPHS), 256, SC_SMEM_BYTES>>>();
    attn_out_kernel<<<dim3(2, N_GRAPHS), 128>>>(out);
}

// round 16
// speedup vs baseline: 1.1485x; 1.1485x over previous
#include <cuda_runtime.h>
#include <cuda_bf16.h>
#include <math.h>
#include <limits.h>

// Problem constants (fixed by the reference)
#define N_NODES    12288
#define N_FEATURES 256
#define KEY_DIM    128
#define N_GRAPHS   192
#define QKV_COLS   512        // [Q(128) | K(128) | V(256)]

#define NGMAX 128

typedef unsigned long long ull;
typedef unsigned int uint;

// bf16 mma (HMMA.16816): D += A(16x16,row) * B(16x8,col), fp32 accum
__device__ __forceinline__ void mma16816(float* c, const uint* a, uint b0, uint b1) {
    asm("mma.sync.aligned.m16n8k16.row.col.f32.bf16.bf16.f32 "
        "{%0,%1,%2,%3}, {%4,%5,%6,%7}, {%8,%9}, {%0,%1,%2,%3};"
        : "+f"(c[0]), "+f"(c[1]), "+f"(c[2]), "+f"(c[3])
        : "r"(a[0]), "r"(a[1]), "r"(a[2]), "r"(a[3]), "r"(b0), "r"(b1));
}

__device__ __forceinline__ unsigned short bfbits(float x) {
    __nv_bfloat16 h = __float2bfloat16_rn(x);
    return *(unsigned short*)&h;
}
__device__ __forceinline__ float bf2f(unsigned short u) {
    __nv_bfloat16 h = *(__nv_bfloat16*)&u;
    return __bfloat162float(h);
}

// Static device scratch (no allocs)
__device__ float  g_QKV[N_NODES * QKV_COLS];                 // 25.2 MB
__device__ int    g_start[N_GRAPHS];
__device__ int    g_end[N_GRAPHS];
__device__ unsigned short g_Xhi[N_NODES * N_FEATURES];       // 6.3 MB
__device__ unsigned short g_Xlo[N_NODES * N_FEATURES];       // 6.3 MB
__device__ unsigned short g_WhiT[QKV_COLS * N_FEATURES];     // 256 KB, [col][k]
__device__ unsigned short g_WloT[QKV_COLS * N_FEATURES];     // 256 KB

// ---------------------------------------------------------------------------
// Kernel 0: init per-graph ranges
// ---------------------------------------------------------------------------
__global__ void init_ranges_kernel() {
    int g = blockIdx.x * blockDim.x + threadIdx.x;
    if (g < N_GRAPHS) {
        g_start[g] = INT_MAX;
        g_end[g]   = 0;
    }
}

// ---------------------------------------------------------------------------
// Kernel 1: per-graph [start, end) from sorted batch (robust to int32/int64)
// ---------------------------------------------------------------------------
__global__ void compute_ranges_kernel(const void* __restrict__ batch) {
    int i = blockIdx.x * blockDim.x + threadIdx.x;
    if (i >= N_NODES) return;
    const long long* b64 = (const long long*)batch;
    long long probe = b64[N_NODES / 4];
    bool is32 = (probe < 0) || (probe >= (long long)N_GRAPHS);
    int g = is32 ? ((const int*)batch)[i] : (int)b64[i];
    if (g < 0 || g >= N_GRAPHS) return;   // defensive
    atomicMin(&g_start[g], i);
    atomicMax(&g_end[g], i + 1);
}

// ---------------------------------------------------------------------------
// Kernel 2a: split X into bf16 hi/lo (row-major, same layout as X)
// ---------------------------------------------------------------------------
__global__ __launch_bounds__(256)
void split_x_kernel(const float* __restrict__ X) {
    int t = blockIdx.x * 256 + threadIdx.x;      // one float4 per thread
    if (t >= N_NODES * N_FEATURES / 4) return;
    float4 v = ((const float4*)X)[t];
    ushort4 h, l;
    h.x = bfbits(v.x); l.x = bfbits(v.x - bf2f(h.x));
    h.y = bfbits(v.y); l.y = bfbits(v.y - bf2f(h.y));
    h.z = bfbits(v.z); l.z = bfbits(v.z - bf2f(h.z));
    h.w = bfbits(v.w); l.w = bfbits(v.w - bf2f(h.w));
    *(ushort4*)&g_Xhi[t * 4] = h;
    *(ushort4*)&g_Xlo[t * 4] = l;
}

// ---------------------------------------------------------------------------
// Kernel 2b: split + transpose W into [col 512][k 256] bf16 hi/lo.
// ---------------------------------------------------------------------------
__global__ __launch_bounds__(256)
void split_w_kernel(const float* __restrict__ Wq,
                    const float* __restrict__ Wk,
                    const float* __restrict__ Wv) {
    int t = blockIdx.x * 256 + threadIdx.x;      // 512 cols x 32 k-chunks
    if (t >= QKV_COLS * (N_FEATURES / 8)) return;
    int col = t >> 5;
    int k0  = (t & 31) * 8;
    const float* W; int ldw, cl;
    if (col < 128)      { W = Wq; ldw = KEY_DIM;    cl = col;       }
    else if (col < 256) { W = Wk; ldw = KEY_DIM;    cl = col - 128; }
    else                { W = Wv; ldw = N_FEATURES; cl = col - 256; }
    unsigned short hs[8], ls[8];
#pragma unroll
    for (int i = 0; i < 8; i++) {
        float x = W[(k0 + i) * ldw + cl];
        hs[i] = bfbits(x);
        ls[i] = bfbits(x - bf2f(hs[i]));
    }
    *(ushort4*)&g_WhiT[col * N_FEATURES + k0]     = make_ushort4(hs[0], hs[1], hs[2], hs[3]);
    *(ushort4*)&g_WhiT[col * N_FEATURES + k0 + 4] = make_ushort4(hs[4], hs[5], hs[6], hs[7]);
    *(ushort4*)&g_WloT[col * N_FEATURES + k0]     = make_ushort4(ls[0], ls[1], ls[2], ls[3]);
    *(ushort4*)&g_WloT[col * N_FEATURES + k0 + 4] = make_ushort4(ls[4], ls[5], ls[6], ls[7]);
}

// ---------------------------------------------------------------------------
// Kernel 3: tensor-core QKV GEMM (bf16-split, 3 passes) — unchanged (proven).
// ---------------------------------------------------------------------------
#define BKP 40

__global__ __launch_bounds__(256)
void qkv_gemm_tc_kernel() {
    __shared__ unsigned short Ahi[128 * BKP], Alo[128 * BKP];
    __shared__ unsigned short Bhi[128 * BKP], Blo[128 * BKP];

    const int bx = blockIdx.x;
    const int by = blockIdx.y;
    const int tid  = threadIdx.x;
    const int wid  = tid >> 5;
    const int lane = tid & 31;
    const int warp_m = wid >> 1;
    const int warp_n = wid & 1;
    const int groupID = lane >> 2;
    const int tig     = lane & 3;
    const int row0  = by * 128;
    const int ncol0 = bx * 128;

    float acc[2][8][4];
#pragma unroll
    for (int am = 0; am < 2; am++)
#pragma unroll
        for (int an = 0; an < 8; an++)
#pragma unroll
            for (int q = 0; q < 4; q++) acc[am][an][q] = 0.0f;

    for (int tile = 0; tile < N_FEATURES / 32; tile++) {
        const int k0 = tile * 32;
        __syncthreads();
#pragma unroll
        for (int t = tid; t < 512; t += 256) {
            int r = t >> 2, c = (t & 3) * 8;
            *(uint4*)&Ahi[r * BKP + c] =
                *(const uint4*)&g_Xhi[(row0 + r) * N_FEATURES + k0 + c];
            *(uint4*)&Alo[r * BKP + c] =
                *(const uint4*)&g_Xlo[(row0 + r) * N_FEATURES + k0 + c];
        }
#pragma unroll
        for (int t = tid; t < 512; t += 256) {
            int nn = t >> 2, c = (t & 3) * 8;
            *(uint4*)&Bhi[nn * BKP + c] =
                *(const uint4*)&g_WhiT[(ncol0 + nn) * N_FEATURES + k0 + c];
            *(uint4*)&Blo[nn * BKP + c] =
                *(const uint4*)&g_WloT[(ncol0 + nn) * N_FEATURES + k0 + c];
        }
        __syncthreads();

#pragma unroll
        for (int ks = 0; ks < 32; ks += 16) {
            uint ahi[2][4], alo[2][4];
#pragma unroll
            for (int am = 0; am < 2; am++) {
                int row = warp_m * 32 + am * 16 + groupID;
                int base = row * BKP + ks + tig * 2;
                ahi[am][0] = *(const uint*)&Ahi[base];
                ahi[am][1] = *(const uint*)&Ahi[base + 8 * BKP];
                ahi[am][2] = *(const uint*)&Ahi[base + 8];
                ahi[am][3] = *(const uint*)&Ahi[base + 8 * BKP + 8];
                alo[am][0] = *(const uint*)&Alo[base];
                alo[am][1] = *(const uint*)&Alo[base + 8 * BKP];
                alo[am][2] = *(const uint*)&Alo[base + 8];
                alo[am][3] = *(const uint*)&Alo[base + 8 * BKP + 8];
            }
#pragma unroll
            for (int an = 0; an < 8; an++) {
                int nn = warp_n * 64 + an * 8 + groupID;
                int nb = nn * BKP + ks + tig * 2;
                uint bh0 = *(const uint*)&Bhi[nb];
                uint bh1 = *(const uint*)&Bhi[nb + 8];
                uint bl0 = *(const uint*)&Blo[nb];
                uint bl1 = *(const uint*)&Blo[nb + 8];
#pragma unroll
                for (int am = 0; am < 2; am++) {
                    mma16816(acc[am][an], ahi[am], bh0, bh1);
                    mma16816(acc[am][an], ahi[am], bl0, bl1);
                    mma16816(acc[am][an], alo[am], bh0, bh1);
                }
            }
        }
    }

#pragma unroll
    for (int am = 0; am < 2; am++) {
#pragma unroll
        for (int an = 0; an < 8; an++) {
            int row = row0 + warp_m * 32 + am * 16 + groupID;
            int col = ncol0 + warp_n * 64 + an * 8 + tig * 2;
            *(float2*)&g_QKV[(size_t)row * QKV_COLS + col] =
                make_float2(acc[am][an][0], acc[am][an][1]);
            *(float2*)&g_QKV[(size_t)(row + 8) * QKV_COLS + col] =
                make_float2(acc[am][an][2], acc[am][an][3]);
        }
    }
}

// ---------------------------------------------------------------------------
// Kernel 4: FUSED tensor-core attention pooling. One CTA (256 thr) per graph.
// S = Q K^T via bf16-split mma (scores in regs), softmax rows (shfl over tig),
// colsum (shfl over groupID + smem cross-warp), fused weighted V sum.
// Warp w owns rows 16w..16w+15; fragments over ceil(n/8) column blocks.
// ---------------------------------------------------------------------------
#define SCP 136     // halfword row stride (128 + 8 pad): conflict-free fragments

#define AT_SMEM_BYTES (4 * NGMAX * SCP * 2 + 8 * NGMAX * 4 + NGMAX * 4)

__global__ __launch_bounds__(256)
void attn_tc_kernel(float* __restrict__ out) {
    extern __shared__ unsigned short smh[];
    unsigned short* sQhi = smh;                   // 128*SCP halves
    unsigned short* sQlo = sQhi + NGMAX * SCP;
    unsigned short* sKhi = sQlo + NGMAX * SCP;
    unsigned short* sKlo = sKhi + NGMAX * SCP;
    float* wcol   = (float*)(sKlo + NGMAX * SCP); // 8*128
    float* colsum = wcol + 8 * NGMAX;             // 128

    const int g    = blockIdx.x;
    const int tid  = threadIdx.x;
    const int w    = tid >> 5;
    const int lane = tid & 31;
    const int groupID = lane >> 2;   // 0..7
    const int tig     = lane & 3;    // 0..3

    int s = g_start[g];
    int n = g_end[g] - s;
    if (n <= 0) {
        out[g * N_FEATURES + tid] = 0.0f;
        return;
    }
    if (n > NGMAX) n = NGMAX;

    // Load Q,K rows (fp32) and convert to bf16 hi/lo in smem
    for (int t = tid; t < n * 32; t += 256) {        // 32 float4 per row
        int j  = t >> 5;
        int kq = (t & 31) * 4;
        float4 q = *(const float4*)&g_QKV[(size_t)(s + j) * QKV_COLS + kq];
        float4 k = *(const float4*)&g_QKV[(size_t)(s + j) * QKV_COLS + KEY_DIM + kq];
        ushort4 qh, ql, kh, kl;
        qh.x = bfbits(q.x); ql.x = bfbits(q.x - bf2f(qh.x));
        qh.y = bfbits(q.y); ql.y = bfbits(q.y - bf2f(qh.y));
        qh.z = bfbits(q.z); ql.z = bfbits(q.z - bf2f(qh.z));
        qh.w = bfbits(q.w); ql.w = bfbits(q.w - bf2f(qh.w));
        kh.x = bfbits(k.x); kl.x = bfbits(k.x - bf2f(kh.x));
        kh.y = bfbits(k.y); kl.y = bfbits(k.y - bf2f(kh.y));
        kh.z = bfbits(k.z); kl.z = bfbits(k.z - bf2f(kh.z));
        kh.w = bfbits(k.w); kl.w = bfbits(k.w - bf2f(kh.w));
        *(ushort4*)&sQhi[j * SCP + kq] = qh;
        *(ushort4*)&sQlo[j * SCP + kq] = ql;
        *(ushort4*)&sKhi[j * SCP + kq] = kh;
        *(ushort4*)&sKlo[j * SCP + kq] = kl;
    }
    __syncthreads();

    const int an_max = (n + 7) >> 3;      // <=16 column fragments
    const int rbase  = w * 16;
    const bool warp_active = (rbase < n);

    float sc[16][4];
#pragma unroll
    for (int an = 0; an < 16; an++)
#pragma unroll
        for (int q = 0; q < 4; q++) sc[an][q] = 0.0f;

    if (warp_active) {
#pragma unroll
        for (int ks = 0; ks < 8; ks++) {         // k16 steps over d=128
            const int kofs = ks * 16 + tig * 2;
            const int abase = (rbase + groupID) * SCP + kofs;
            uint ah[4], al[4];
            ah[0] = *(const uint*)&sQhi[abase];
            ah[1] = *(const uint*)&sQhi[abase + 8 * SCP];
            ah[2] = *(const uint*)&sQhi[abase + 8];
            ah[3] = *(const uint*)&sQhi[abase + 8 * SCP + 8];
            al[0] = *(const uint*)&sQlo[abase];
            al[1] = *(const uint*)&sQlo[abase + 8 * SCP];
            al[2] = *(const uint*)&sQlo[abase + 8];
            al[3] = *(const uint*)&sQlo[abase + 8 * SCP + 8];
#pragma unroll
            for (int an = 0; an < 16; an++) {
                if (an < an_max) {
                    int nb = (an * 8 + groupID) * SCP + kofs;
                    uint bh0 = *(const uint*)&sKhi[nb];
                    uint bh1 = *(const uint*)&sKhi[nb + 8];
                    uint bl0 = *(const uint*)&sKlo[nb];
                    uint bl1 = *(const uint*)&sKlo[nb + 8];
                    mma16816(sc[an], ah, bh0, bh1);
                    mma16816(sc[an], ah, bl0, bl1);
                    mma16816(sc[an], al, bh0, bh1);
                }
            }
        }

        // ----- softmax over rows r0 = rbase+groupID, r1 = r0+8 -----
        const int r0 = rbase + groupID;
        const int r1 = r0 + 8;
        const bool v0 = (r0 < n), v1 = (r1 < n);

        // scale + column mask (also squashes any NaN from uninit smem)
#pragma unroll
        for (int an = 0; an < 16; an++) {
            if (an < an_max) {
                int c0 = an * 8 + tig * 2;
#pragma unroll
                for (int p = 0; p < 2; p++) {
                    bool cv = (c0 + p) < n;
                    sc[an][p]     = cv ? sc[an][p]     * 0.0625f : -1e30f;
                    sc[an][p + 2] = cv ? sc[an][p + 2] * 0.0625f : -1e30f;
                }
            }
        }
        // row max
        float m0 = -1e30f, m1 = -1e30f;
#pragma unroll
        for (int an = 0; an < 16; an++) {
            if (an < an_max) {
                m0 = fmaxf(m0, fmaxf(sc[an][0], sc[an][1]));
                m1 = fmaxf(m1, fmaxf(sc[an][2], sc[an][3]));
            }
        }
#pragma unroll
        for (int o = 1; o <= 2; o <<= 1) {
            m0 = fmaxf(m0, __shfl_xor_sync(0xffffffffu, m0, o));
            m1 = fmaxf(m1, __shfl_xor_sync(0xffffffffu, m1, o));
        }
        // exp + row sum
        float s0 = 0.0f, s1 = 0.0f;
#pragma unroll
        for (int an = 0; an < 16; an++) {
            if (an < an_max) {
                sc[an][0] = __expf(sc[an][0] - m0);
                sc[an][1] = __expf(sc[an][1] - m0);
                sc[an][2] = __expf(sc[an][2] - m1);
                sc[an][3] = __expf(sc[an][3] - m1);
                s0 += sc[an][0] + sc[an][1];
                s1 += sc[an][2] + sc[an][3];
            }
        }
#pragma unroll
        for (int o = 1; o <= 2; o <<= 1) {
            s0 += __shfl_xor_sync(0xffffffffu, s0, o);
            s1 += __shfl_xor_sync(0xffffffffu, s1, o);
        }
        const float i0 = v0 ? (1.0f / s0) : 0.0f;
        const float i1 = v1 ? (1.0f / s1) : 0.0f;

        // colsum partials: reduce over groupID (lanes xor 4,8,16)
#pragma unroll
        for (int an = 0; an < 16; an++) {
            if (an < an_max) {
#pragma unroll
                for (int p = 0; p < 2; p++) {
                    float v = sc[an][p] * i0 + sc[an][p + 2] * i1;
#pragma unroll
                    for (int o = 4; o <= 16; o <<= 1)
                        v += __shfl_xor_sync(0xffffffffu, v, o);
                    if (groupID == 0)
                        wcol[w * NGMAX + an * 8 + tig * 2 + p] = v;
                }
            }
        }
    }
    __syncthreads();

    // Cross-warp colsum reduce (only warps whose row block intersects [0,n))
    const int nw = (n + 15) >> 4;
    for (int j = tid; j < n; j += 256) {
        float t = 0.0f;
        for (int ww = 0; ww < nw; ww++) t += wcol[ww * NGMAX + j];
        colsum[j] = t;
    }
    __syncthreads();

    // Fused weighted V sum: thread = feature (coalesced), 4-way MLP
    const int f = tid;
    const float* Vb = &g_QKV[(size_t)s * QKV_COLS + 2 * KEY_DIM + f];
    float a0 = 0.0f, a1 = 0.0f, a2 = 0.0f, a3 = 0.0f;
    int j = 0;
    for (; j + 3 < n; j += 4) {
        a0 += colsum[j + 0] * Vb[(size_t)(j + 0) * QKV_COLS];
        a1 += colsum[j + 1] * Vb[(size_t)(j + 1) * QKV_COLS];
        a2 += colsum[j + 2] * Vb[(size_t)(j + 2) * QKV_COLS];
        a3 += colsum[j + 3] * Vb[(size_t)(j + 3) * QKV_COLS];
    }
    for (; j < n; j++) a0 += colsum[j] * Vb[(size_t)j * QKV_COLS];
    out[g * N_FEATURES + f] = (a0 + a1) + (a2 + a3);
}

// ---------------------------------------------------------------------------
// Launch
// ---------------------------------------------------------------------------
extern "C" void kernel_launch(void* const* d_in, const int* in_sizes, int n_in,
                              void* d_out, int out_size) {
    const float* X  = (const float*)d_in[0];
    const void*  batch = d_in[1];
    const float* Wq = (const float*)d_in[2];
    const float* Wk = (const float*)d_in[3];
    const float* Wv = (const float*)d_in[4];
    float* out = (float*)d_out;

    cudaFuncSetAttribute(attn_tc_kernel,
                         cudaFuncAttributeMaxDynamicSharedMemorySize,
                         AT_SMEM_BYTES);

    init_ranges_kernel<<<1, N_GRAPHS>>>();
    compute_ranges_kernel<<<(N_NODES + 255) / 256, 256>>>(batch);
    split_x_kernel<<<(N_NODES * N_FEATURES / 4 + 255) / 256, 256>>>(X);
    split_w_kernel<<<(QKV_COLS * (N_FEATURES / 8) + 255) / 256, 256>>>(Wq, Wk, Wv);
    qkv_gemm_tc_kernel<<<dim3(4, N_NODES / 128), 256>>>();
    attn_tc_kernel<<<N_GRAPHS, 256, AT_SMEM_BYTES>>>(out);
}